// round 11
// baseline (speedup 1.0000x reference)
#include <cuda_runtime.h>
#include <cstdint>
#include <math.h>

#define BB 16
#define NN 2048
#define BN (BB*NN)
#define KNBR 20

typedef unsigned long long ull;
// packed fp32x2 helpers (sm_100+; ptxas never auto-fuses these)
#define FMA2(d, a, b) asm("fma.rn.f32x2 %0, %1, %2, %0;" : "+l"(d) : "l"(a), "l"(b))
#define PCK(v, f)     asm("mov.b64 %0, {%1, %1};" : "=l"(v) : "f"(f))
#define UNPK(lo, hi, v) asm("mov.b64 {%0, %1}, %2;" : "=f"(lo), "=f"(hi) : "l"(v))

__device__ float g_xT[BN*2];
__device__ float g_catT[BN*192];
__device__ float g_ac[BN*128];
__device__ float g_big[(size_t)BN*2048];   // dist / e / h7+h8 scratch
__device__ int   g_idx[BN*KNBR];
__device__ float g_nrm[BN];
__device__ float g_gvec[BB*1024];
__device__ float g_part[BB*8*1024];
__device__ float g_gproj[BB*512];
__device__ float g_wst[128*64];

__global__ void k_prep_x(const float* __restrict__ x) {
    int i = blockIdx.x*256 + threadIdx.x;
    if (i >= BN) return;
    int b = i >> 11, n = i & 2047;
    g_xT[i*2]   = x[(size_t)b*2*NN + n];
    g_xT[i*2+1] = x[(size_t)b*2*NN + NN + n];
}

__global__ void k_norm(const float* __restrict__ F, int stride) {
    int i = blockIdx.x*256 + threadIdx.x;
    if (i >= BN) return;
    const float* r = F + (size_t)i*stride;
    float a = 0.f;
    #pragma unroll 16
    for (int c = 0; c < 64; c++) a = fmaf(r[c], r[c], a);
    g_nrm[i] = a;
}

__global__ void k_stack(const float* __restrict__ w) {  // w: (64,128) -> [Wa ; Wb-Wa]
    int i = blockIdx.x*256 + threadIdx.x;
    if (i >= 64*64) return;
    int o = i >> 6, c = i & 63;
    float a  = w[o*128 + c];
    float b2 = w[o*128 + 64 + c];
    g_wst[o*64 + c]      = a;
    g_wst[(64+o)*64 + c] = b2 - a;
}

__global__ void k_ac1(const float* __restrict__ w1) {
    int i = blockIdx.x*256 + threadIdx.x;
    if (i >= BN*64) return;
    int p = i >> 6, o = i & 63;
    float x0 = g_xT[p*2], x1 = g_xT[p*2+1];
    float wa0 = w1[o*4], wa1 = w1[o*4+1], wb0 = w1[o*4+2], wb1 = w1[o*4+3];
    g_ac[(size_t)p*128 + o]      = fmaf(wa0, x0, wa1*x1);
    g_ac[(size_t)p*128 + 64 + o] = fmaf(wb0-wa0, x0, (wb1-wa1)*x1);
}

// tiled fp32 GEMM with packed f32x2 inner loop.
// Y[m][o] = epi(alpha*sum_k X[m][k]*W[b][o][k] + beta*vec[b][o])
// 128x128 tile, K-step 16, 256 threads, 8x8 register tile (packed as 8x4 u64),
// double-buffered smem. K-accumulation order per output is unchanged (pairing is
// across outputs), so results are bitwise identical to the scalar version.
__global__ void __launch_bounds__(256) k_gemm(
    const float* __restrict__ X, int sX,
    const float* __restrict__ W, int sW, long long wbs,
    float* __restrict__ Y, int sY, int K,
    float alpha, const float* __restrict__ vec, float beta, int vecStride,
    const float* __restrict__ s, const float* __restrict__ t, int act)
{
    __shared__ float Xs[2][16][128];
    __shared__ float Ws[2][16][128];
    const int tid = threadIdx.x;
    const int m0 = blockIdx.x * 128;
    const int o0 = blockIdx.y * 128;
    const int b  = m0 >> 11;
    const float* Wb = W + (long long)b * wbs;
    const int xm = tid & 127, xq = tid >> 7;
    const int tx = tid & 15,  ty = tid >> 4;
    const float* xrow = X  + (long long)(m0+xm)*sX;
    const float* wrow = Wb + (long long)(o0+xm)*sW;
    ull acc2[8][4];
    #pragma unroll
    for (int r = 0; r < 8; r++)
        #pragma unroll
        for (int c = 0; c < 4; c++) acc2[r][c] = 0ull;

    float4 xa = *(const float4*)(xrow + xq*4);
    float4 xb = *(const float4*)(xrow + xq*4 + 8);
    float4 wa = *(const float4*)(wrow + xq*4);
    float4 wb = *(const float4*)(wrow + xq*4 + 8);
    #pragma unroll
    for (int u = 0; u < 4; u++) {
        Xs[0][xq*4+u][xm]   = (&xa.x)[u];
        Xs[0][xq*4+8+u][xm] = (&xb.x)[u];
        Ws[0][xq*4+u][xm]   = (&wa.x)[u];
        Ws[0][xq*4+8+u][xm] = (&wb.x)[u];
    }
    __syncthreads();
    int cur = 0;
    for (int k0 = 16; k0 < K; k0 += 16) {
        xa = *(const float4*)(xrow + k0 + xq*4);
        xb = *(const float4*)(xrow + k0 + xq*4 + 8);
        wa = *(const float4*)(wrow + k0 + xq*4);
        wb = *(const float4*)(wrow + k0 + xq*4 + 8);
        #pragma unroll
        for (int kk = 0; kk < 16; kk++) {
            float4 a0 = *(const float4*)&Xs[cur][kk][ty*4];
            float4 a1 = *(const float4*)&Xs[cur][kk][64+ty*4];
            ulonglong2 w0 = *(const ulonglong2*)&Ws[cur][kk][tx*4];
            ulonglong2 w1 = *(const ulonglong2*)&Ws[cur][kk][64+tx*4];
            ull bv2[4] = {w0.x, w0.y, w1.x, w1.y};
            float av[8] = {a0.x,a0.y,a0.z,a0.w,a1.x,a1.y,a1.z,a1.w};
            ull av2[8];
            #pragma unroll
            for (int r = 0; r < 8; r++) PCK(av2[r], av[r]);
            #pragma unroll
            for (int r = 0; r < 8; r++)
                #pragma unroll
                for (int c = 0; c < 4; c++)
                    FMA2(acc2[r][c], av2[r], bv2[c]);
        }
        int nxt = cur ^ 1;
        #pragma unroll
        for (int u = 0; u < 4; u++) {
            Xs[nxt][xq*4+u][xm]   = (&xa.x)[u];
            Xs[nxt][xq*4+8+u][xm] = (&xb.x)[u];
            Ws[nxt][xq*4+u][xm]   = (&wa.x)[u];
            Ws[nxt][xq*4+8+u][xm] = (&wb.x)[u];
        }
        __syncthreads();
        cur = nxt;
    }
    #pragma unroll
    for (int kk = 0; kk < 16; kk++) {
        float4 a0 = *(const float4*)&Xs[cur][kk][ty*4];
        float4 a1 = *(const float4*)&Xs[cur][kk][64+ty*4];
        ulonglong2 w0 = *(const ulonglong2*)&Ws[cur][kk][tx*4];
        ulonglong2 w1 = *(const ulonglong2*)&Ws[cur][kk][64+tx*4];
        ull bv2[4] = {w0.x, w0.y, w1.x, w1.y};
        float av[8] = {a0.x,a0.y,a0.z,a0.w,a1.x,a1.y,a1.z,a1.w};
        ull av2[8];
        #pragma unroll
        for (int r = 0; r < 8; r++) PCK(av2[r], av[r]);
        #pragma unroll
        for (int r = 0; r < 8; r++)
            #pragma unroll
            for (int c = 0; c < 4; c++)
                FMA2(acc2[r][c], av2[r], bv2[c]);
    }

    float vv[8] = {}, ss[8] = {}, tt[8] = {};
    if (vec) {
        *(float4*)&vv[0] = *(const float4*)(vec + b*vecStride + o0 + tx*4);
        *(float4*)&vv[4] = *(const float4*)(vec + b*vecStride + o0 + 64 + tx*4);
    }
    if (act) {
        *(float4*)&ss[0] = *(const float4*)(s + o0 + tx*4);
        *(float4*)&ss[4] = *(const float4*)(s + o0 + 64 + tx*4);
        *(float4*)&tt[0] = *(const float4*)(t + o0 + tx*4);
        *(float4*)&tt[4] = *(const float4*)(t + o0 + 64 + tx*4);
    }
    #pragma unroll
    for (int r = 0; r < 8; r++) {
        int m = m0 + (r < 4 ? ty*4 + r : 64 + ty*4 + r - 4);
        float o4[8];
        #pragma unroll
        for (int c = 0; c < 4; c++) {
            float lo, hi;
            UNPK(lo, hi, acc2[r][c]);
            o4[c*2]   = lo;
            o4[c*2+1] = hi;
        }
        // o4 order: [c0,c1,c2,c3] from w0 pairs -> cols tx*4..tx*4+3; [c4..c7] -> 64+tx*4..
        #pragma unroll
        for (int c = 0; c < 8; c++) {
            float a = alpha * o4[c];
            if (vec) a = fmaf(beta, vv[c], a);
            if (act) { a = fmaf(ss[c], a, tt[c]); a = a > 0.f ? a : 0.2f*a; }
            o4[c] = a;
        }
        *(float4*)(Y + (long long)m*sY + o0 + tx*4)      = *(float4*)&o4[0];
        *(float4*)(Y + (long long)m*sY + o0 + 64 + tx*4) = *(float4*)&o4[4];
    }
}

// per-row top-20, tournament style.
template<int COORD>
__global__ void __launch_bounds__(256) k_topk(const float* __restrict__ dist,
                                              int* __restrict__ idxo) {
    __shared__ float sv[NN];
    __shared__ float tmax[256];
    __shared__ int   targ[256];
    const int row = blockIdx.x, tid = threadIdx.x, b = row >> 11;
    if (COORD) {
        const float2* xp = (const float2*)g_xT + b*NN;
        float2 c = xp[row & 2047];
        for (int j = tid; j < NN; j += 256) {
            float2 q = xp[j];
            float dx = q.x - c.x, dy = q.y - c.y;
            sv[j] = -fmaf(dx, dx, dy*dy);
        }
    } else {
        const float* d = dist + (size_t)row * NN;
        for (int j = tid; j < NN; j += 256) sv[j] = d[j];
    }
    float lm = -INFINITY; int la = tid;
    for (int j = tid; j < NN; j += 256) {
        float v = sv[j];
        if (v > lm) { lm = v; la = j; }
    }
    tmax[tid] = lm; targ[tid] = la;
    __syncthreads();
    if (tid < 32) {
        for (int k = 0; k < KNBR; k++) {
            float bv = -INFINITY; int bt = tid;
            #pragma unroll
            for (int j = 0; j < 8; j++) {
                float v = tmax[tid + 32*j];
                if (v > bv) { bv = v; bt = tid + 32*j; }
            }
            #pragma unroll
            for (int off = 16; off; off >>= 1) {
                float ov = __shfl_down_sync(0xffffffffu, bv, off);
                int   ot = __shfl_down_sync(0xffffffffu, bt, off);
                if (ov > bv) { bv = ov; bt = ot; }
            }
            bt = __shfl_sync(0xffffffffu, bt, 0);
            if (tid == 0) {
                int gi = targ[bt];
                idxo[(size_t)row*KNBR + k] = gi;
                sv[gi] = -INFINITY;
                float lm2 = -INFINITY; int la2 = bt;
                for (int i = bt; i < NN; i += 256) {
                    float v = sv[i];
                    if (v > lm2) { lm2 = v; la2 = i; }
                }
                tmax[bt] = lm2; targ[bt] = la2;
            }
            __syncwarp();
        }
    }
}

// fused edge conv: 32 points/block; conv2 inner loop packed f32x2 over points.
template<bool TWO>
__global__ void __launch_bounds__(256) k_edge(
    const int* __restrict__ idx, const float* __restrict__ w2,
    const float* __restrict__ s1v, const float* __restrict__ t1v,
    const float* __restrict__ s2v, const float* __restrict__ t2v,
    float* __restrict__ outB, int outOff)
{
    __shared__ float W2s[64*65];
    __shared__ float h1T[4][64*8];
    const int tid = threadIdx.x;
    const int g = tid >> 6, o = tid & 63;
    const int n0 = blockIdx.x*32 + g*8;
    const int b  = n0 >> 11;
    if (TWO) for (int i = tid; i < 4096; i += 256) W2s[(i>>6)*65 + (i&63)] = w2[i];
    float cv[8], mv[8];
    #pragma unroll
    for (int p = 0; p < 8; p++) {
        cv[p] = g_ac[(size_t)(n0+p)*128 + 64 + o];
        mv[p] = -INFINITY;
    }
    const float ls1 = s1v[o], lt1 = t1v[o];
    float ls2 = 0.f, lt2 = 0.f;
    if (TWO) { ls2 = s2v[o]; lt2 = t2v[o]; __syncthreads(); }
    for (int k = 0; k < KNBR; k++) {
        float hv[8];
        #pragma unroll
        for (int p = 0; p < 8; p++) {
            int j = idx[(size_t)(n0+p)*KNBR + k];
            float aj = g_ac[(size_t)(b*NN + j)*128 + o];
            float h = fmaf(ls1, aj + cv[p], lt1);
            hv[p] = h > 0.f ? h : 0.2f*h;
        }
        if (TWO) {
            __syncthreads();
            *(float4*)&h1T[g][o*8]   = make_float4(hv[0],hv[1],hv[2],hv[3]);
            *(float4*)&h1T[g][o*8+4] = make_float4(hv[4],hv[5],hv[6],hv[7]);
            __syncthreads();
            ull y2[4] = {0ull, 0ull, 0ull, 0ull};
            #pragma unroll 8
            for (int c = 0; c < 64; c++) {
                ull wp; PCK(wp, W2s[o*65 + c]);
                ulonglong2 A0 = *(const ulonglong2*)&h1T[g][c*8];
                ulonglong2 A1 = *(const ulonglong2*)&h1T[g][c*8+4];
                FMA2(y2[0], wp, A0.x);
                FMA2(y2[1], wp, A0.y);
                FMA2(y2[2], wp, A1.x);
                FMA2(y2[3], wp, A1.y);
            }
            float y[8];
            #pragma unroll
            for (int q = 0; q < 4; q++) { UNPK(y[q*2], y[q*2+1], y2[q]); }
            #pragma unroll
            for (int p = 0; p < 8; p++) {
                float z = fmaf(ls2, y[p], lt2);
                z = z > 0.f ? z : 0.2f*z;
                mv[p] = fmaxf(mv[p], z);
            }
        } else {
            #pragma unroll
            for (int p = 0; p < 8; p++) mv[p] = fmaxf(mv[p], hv[p]);
        }
    }
    #pragma unroll
    for (int p = 0; p < 8; p++) outB[(size_t)(n0+p)*192 + outOff + o] = mv[p];
}

__global__ void k_maxn1() {
    int o = blockIdx.x*256 + threadIdx.x;
    int b = blockIdx.y, ch = blockIdx.z;
    const float* p = g_big + (size_t)(b*NN + ch*256)*1024 + o;
    float m = -INFINITY;
    #pragma unroll 8
    for (int n = 0; n < 256; n++) m = fmaxf(m, p[(size_t)n*1024]);
    g_part[(b*8+ch)*1024 + o] = m;
}
__global__ void k_maxn2() {
    int o = blockIdx.x*256 + threadIdx.x;
    int b = blockIdx.y;
    float m = -INFINITY;
    #pragma unroll
    for (int ch = 0; ch < 8; ch++) m = fmaxf(m, g_part[(b*8+ch)*1024 + o]);
    g_gvec[b*1024 + o] = m;
}
__global__ void k_gproj(const float* __restrict__ w7) {
    int b = blockIdx.x, o = threadIdx.x;       // 512 threads
    __shared__ float gs[1024];
    for (int c = threadIdx.x; c < 1024; c += 512) gs[c] = g_gvec[b*1024 + c];
    __syncthreads();
    const float* wr = w7 + (size_t)o*1216;
    float a = 0.f;
    #pragma unroll 16
    for (int c = 0; c < 1024; c++) a = fmaf(wr[c], gs[c], a);
    g_gproj[b*512 + o] = a;
}
__global__ void k_final(const float* __restrict__ w9, const float* __restrict__ h8,
                        float* __restrict__ out) {
    int pt = blockIdx.x*8 + (threadIdx.x >> 5);
    int lane = threadIdx.x & 31;
    const float* r = h8 + (size_t)pt*256;
    float a = 0.f;
    #pragma unroll
    for (int u = 0; u < 8; u++) a = fmaf(r[lane + u*32], w9[lane + u*32], a);
    #pragma unroll
    for (int off = 16; off; off >>= 1) a += __shfl_down_sync(0xffffffffu, a, off);
    if (lane == 0) out[pt] = 1.f / (1.f + expf(-a));
}

extern "C" void kernel_launch(void* const* d_in, const int* in_sizes, int n_in,
                              void* d_out, int out_size)
{
    (void)in_sizes; (void)n_in; (void)out_size;
    const float* x = (const float*)d_in[0];
    const float *w1=(const float*)d_in[1], *w2=(const float*)d_in[2], *w3=(const float*)d_in[3],
                *w4=(const float*)d_in[4], *w5=(const float*)d_in[5], *w6=(const float*)d_in[6],
                *w7=(const float*)d_in[7], *w8=(const float*)d_in[8], *w9=(const float*)d_in[9];
    // metadata order follows setup_inputs() dict insertion: s/t INTERLEAVED: s1,t1,s2,t2,...
    const float *s1=(const float*)d_in[10], *t1=(const float*)d_in[11],
                *s2=(const float*)d_in[12], *t2=(const float*)d_in[13],
                *s3=(const float*)d_in[14], *t3=(const float*)d_in[15],
                *s4=(const float*)d_in[16], *t4=(const float*)d_in[17],
                *s5=(const float*)d_in[18], *t5=(const float*)d_in[19],
                *s6=(const float*)d_in[20], *t6=(const float*)d_in[21],
                *s7=(const float*)d_in[22], *t7=(const float*)d_in[23],
                *s8=(const float*)d_in[24], *t8=(const float*)d_in[25];
    float* out = (float*)d_out;

    float *p_catT, *p_big, *p_nrm, *p_wst, *p_gproj, *p_ac; int* p_idx;
    cudaGetSymbolAddress((void**)&p_catT,  g_catT);
    cudaGetSymbolAddress((void**)&p_big,   g_big);
    cudaGetSymbolAddress((void**)&p_nrm,   g_nrm);
    cudaGetSymbolAddress((void**)&p_wst,   g_wst);
    cudaGetSymbolAddress((void**)&p_gproj, g_gproj);
    cudaGetSymbolAddress((void**)&p_ac,    g_ac);
    cudaGetSymbolAddress((void**)&p_idx,   g_idx);
    float* p_h8 = p_big + (size_t)BN*512;

    k_prep_x<<<BN/256, 256>>>(x);
    // ---- stage 1 (C=2) ----
    k_topk<1><<<BN, 256>>>(nullptr, p_idx);
    k_ac1<<<BN*64/256, 256>>>(w1);
    k_edge<true><<<BN/32, 256>>>(p_idx, w2, s1, t1, s2, t2, p_catT, 0);
    // ---- stage 2 (input x1 = catT[:,0:64)) ----
    k_norm<<<BN/256, 256>>>(p_catT, 192);
    k_stack<<<16, 256>>>(w3);
    k_gemm<<<dim3(256,16),256>>>(p_catT,192, p_catT,192,(long long)NN*192,
                                 p_big,2048, 64, 2.f, p_nrm,-1.f,2048, nullptr,nullptr,0);
    k_topk<0><<<BN, 256>>>(p_big, p_idx);
    k_gemm<<<dim3(256,1),256>>>(p_catT,192, p_wst,64,0,
                                p_ac,128, 64, 1.f, nullptr,0.f,0, nullptr,nullptr,0);
    k_edge<true><<<BN/32, 256>>>(p_idx, w4, s3, t3, s4, t4, p_catT, 64);
    // ---- stage 3 (input x2 = catT[:,64:128)) ----
    k_norm<<<BN/256, 256>>>(p_catT+64, 192);
    k_stack<<<16, 256>>>(w5);
    k_gemm<<<dim3(256,16),256>>>(p_catT+64,192, p_catT+64,192,(long long)NN*192,
                                 p_big,2048, 64, 2.f, p_nrm,-1.f,2048, nullptr,nullptr,0);
    k_topk<0><<<BN, 256>>>(p_big, p_idx);
    k_gemm<<<dim3(256,1),256>>>(p_catT+64,192, p_wst,64,0,
                                p_ac,128, 64, 1.f, nullptr,0.f,0, nullptr,nullptr,0);
    k_edge<false><<<BN/32, 256>>>(p_idx, nullptr, s5, t5, nullptr, nullptr, p_catT, 128);
    // ---- head ----
    k_gemm<<<dim3(256,8),256>>>(p_catT,192, w6,192,0,
                                p_big,1024, 192, 1.f, nullptr,0.f,0, s6,t6,1);
    k_maxn1<<<dim3(4,16,8), 256>>>();
    k_maxn2<<<dim3(4,16), 256>>>();
    k_gproj<<<16, 512>>>(w7);
    k_gemm<<<dim3(256,4),256>>>(p_catT,192, w7+1024,1216,0,
                                p_big,512, 192, 1.f, p_gproj,1.f,512, s7,t7,1);
    k_gemm<<<dim3(256,2),256>>>(p_big,512, w8,512,0,
                                p_h8,256, 512, 1.f, nullptr,0.f,0, s8,t8,1);
    k_final<<<BN/8, 256>>>(w9, p_h8, out);
}

// round 16
// speedup vs baseline: 1.6441x; 1.6441x over previous
#include <cuda_runtime.h>
#include <cstdint>
#include <math.h>

#define BB 16
#define NN 2048
#define BN (BB*NN)
#define KNBR 20

__device__ float g_xT[BN*2];
__device__ float g_catT[BN*192];
__device__ float g_ac[BN*128];
__device__ float g_big[(size_t)BN*2048];   // dist / e / h7+h8 scratch
__device__ int   g_idx[BN*KNBR];
__device__ float g_nrm[BN];
__device__ float g_gvec[BB*1024];
__device__ float g_part[BB*8*1024];
__device__ float g_gproj[BB*512];
__device__ float g_wst[128*64];

__global__ void k_prep_x(const float* __restrict__ x) {
    int i = blockIdx.x*256 + threadIdx.x;
    if (i >= BN) return;
    int b = i >> 11, n = i & 2047;
    g_xT[i*2]   = x[(size_t)b*2*NN + n];
    g_xT[i*2+1] = x[(size_t)b*2*NN + NN + n];
}

__global__ void k_norm(const float* __restrict__ F, int stride) {
    int i = blockIdx.x*256 + threadIdx.x;
    if (i >= BN) return;
    const float* r = F + (size_t)i*stride;
    float a = 0.f;
    #pragma unroll 16
    for (int c = 0; c < 64; c++) a = fmaf(r[c], r[c], a);
    g_nrm[i] = a;
}

__global__ void k_stack(const float* __restrict__ w) {  // w: (64,128) -> [Wa ; Wb-Wa]
    int i = blockIdx.x*256 + threadIdx.x;
    if (i >= 64*64) return;
    int o = i >> 6, c = i & 63;
    float a  = w[o*128 + c];
    float b2 = w[o*128 + 64 + c];
    g_wst[o*64 + c]      = a;
    g_wst[(64+o)*64 + c] = b2 - a;
}

__global__ void k_ac1(const float* __restrict__ w1) {
    int i = blockIdx.x*256 + threadIdx.x;
    if (i >= BN*64) return;
    int p = i >> 6, o = i & 63;
    float x0 = g_xT[p*2], x1 = g_xT[p*2+1];
    float wa0 = w1[o*4], wa1 = w1[o*4+1], wb0 = w1[o*4+2], wb1 = w1[o*4+3];
    g_ac[(size_t)p*128 + o]      = fmaf(wa0, x0, wa1*x1);
    g_ac[(size_t)p*128 + 64 + o] = fmaf(wb0-wa0, x0, (wb1-wa1)*x1);
}

// ---------- symmetric dist GEMM: S[b] = 2*F F^T - nrm_j, upper-triangle tiles only ----------
// 128x128 tile, K=64, 256 threads, 8x8 register tile, double-buffered smem.
// Off-diagonal tiles also write the mirrored tile via smem-staged transpose.
// NOTE: Ts pad must be a multiple of 4 floats (float4 reads per row) -> 132.
__global__ void __launch_bounds__(256) k_dist(
    const float* __restrict__ F, int ldf, float* __restrict__ out)
{
    __shared__ float Xs[2][16][128];
    __shared__ float Ws[2][16][128];
    __shared__ float Ts[64][132];
    const int tid = threadIdx.x;
    int t = blockIdx.x;
    int j = (int)((sqrtf(8.f*(float)t + 1.f) - 1.f) * 0.5f);
    while ((j+1)*(j+2)/2 <= t) j++;
    while (j*(j+1)/2 > t) j--;
    const int i = t - j*(j+1)/2;          // i <= j
    const int m0 = i*128, n0 = j*128, b = blockIdx.y;
    const float* Fb = F + (size_t)b*NN*ldf;
    const int xm = tid & 127, xq = tid >> 7;
    const int tx = tid & 15,  ty = tid >> 4;
    const float* xrow = Fb + (size_t)(m0+xm)*ldf;
    const float* wrow = Fb + (size_t)(n0+xm)*ldf;
    float acc[8][8] = {};

    float4 xa = *(const float4*)(xrow + xq*4);
    float4 xb = *(const float4*)(xrow + xq*4 + 8);
    float4 wa = *(const float4*)(wrow + xq*4);
    float4 wb = *(const float4*)(wrow + xq*4 + 8);
    #pragma unroll
    for (int u = 0; u < 4; u++) {
        Xs[0][xq*4+u][xm]   = (&xa.x)[u];
        Xs[0][xq*4+8+u][xm] = (&xb.x)[u];
        Ws[0][xq*4+u][xm]   = (&wa.x)[u];
        Ws[0][xq*4+8+u][xm] = (&wb.x)[u];
    }
    __syncthreads();
    int cur = 0;
    for (int k0 = 16; k0 < 64; k0 += 16) {
        xa = *(const float4*)(xrow + k0 + xq*4);
        xb = *(const float4*)(xrow + k0 + xq*4 + 8);
        wa = *(const float4*)(wrow + k0 + xq*4);
        wb = *(const float4*)(wrow + k0 + xq*4 + 8);
        #pragma unroll
        for (int kk = 0; kk < 16; kk++) {
            float4 a0 = *(const float4*)&Xs[cur][kk][ty*4];
            float4 a1 = *(const float4*)&Xs[cur][kk][64+ty*4];
            float4 b0 = *(const float4*)&Ws[cur][kk][tx*4];
            float4 b1 = *(const float4*)&Ws[cur][kk][64+tx*4];
            float av[8] = {a0.x,a0.y,a0.z,a0.w,a1.x,a1.y,a1.z,a1.w};
            float bv[8] = {b0.x,b0.y,b0.z,b0.w,b1.x,b1.y,b1.z,b1.w};
            #pragma unroll
            for (int r = 0; r < 8; r++)
                #pragma unroll
                for (int c = 0; c < 8; c++)
                    acc[r][c] = fmaf(av[r], bv[c], acc[r][c]);
        }
        int nxt = cur ^ 1;
        #pragma unroll
        for (int u = 0; u < 4; u++) {
            Xs[nxt][xq*4+u][xm]   = (&xa.x)[u];
            Xs[nxt][xq*4+8+u][xm] = (&xb.x)[u];
            Ws[nxt][xq*4+u][xm]   = (&wa.x)[u];
            Ws[nxt][xq*4+8+u][xm] = (&wb.x)[u];
        }
        __syncthreads();
        cur = nxt;
    }
    #pragma unroll
    for (int kk = 0; kk < 16; kk++) {
        float4 a0 = *(const float4*)&Xs[cur][kk][ty*4];
        float4 a1 = *(const float4*)&Xs[cur][kk][64+ty*4];
        float4 b0 = *(const float4*)&Ws[cur][kk][tx*4];
        float4 b1 = *(const float4*)&Ws[cur][kk][64+tx*4];
        float av[8] = {a0.x,a0.y,a0.z,a0.w,a1.x,a1.y,a1.z,a1.w};
        float bv[8] = {b0.x,b0.y,b0.z,b0.w,b1.x,b1.y,b1.z,b1.w};
        #pragma unroll
        for (int r = 0; r < 8; r++)
            #pragma unroll
            for (int c = 0; c < 8; c++)
                acc[r][c] = fmaf(av[r], bv[c], acc[r][c]);
    }

    // normal write: rows m0+.., cols n0+..: 2*acc - nrm[n]
    {
        float vv[8];
        *(float4*)&vv[0] = *(const float4*)(g_nrm + b*NN + n0 + tx*4);
        *(float4*)&vv[4] = *(const float4*)(g_nrm + b*NN + n0 + 64 + tx*4);
        #pragma unroll
        for (int r = 0; r < 8; r++) {
            int m = m0 + (r < 4 ? ty*4 + r : 64 + ty*4 + r - 4);
            float o4[8];
            #pragma unroll
            for (int c = 0; c < 8; c++) o4[c] = fmaf(2.f, acc[r][c], -vv[c]);
            *(float4*)(out + ((size_t)b*NN + m)*NN + n0 + tx*4)      = *(float4*)&o4[0];
            *(float4*)(out + ((size_t)b*NN + m)*NN + n0 + 64 + tx*4) = *(float4*)&o4[4];
        }
    }
    // mirrored write for off-diagonal tiles: rows n0+.., cols m0+..: 2*acc^T - nrm[m]
    if (i < j) {
        #pragma unroll
        for (int h = 0; h < 2; h++) {
            __syncthreads();
            #pragma unroll
            for (int r = 0; r < 8; r++) {
                int ml = (r < 4 ? ty*4 + r : 64 + ty*4 + r - 4);
                #pragma unroll
                for (int c = 0; c < 4; c++)
                    Ts[tx*4 + c][ml] = acc[r][h*4 + c];
            }
            __syncthreads();
            int rr = tid >> 2, seg = tid & 3;
            int grow = n0 + h*64 + rr;
            #pragma unroll
            for (int u = 0; u < 8; u++) {
                int col = seg*4 + u*16;
                float4 v = *(const float4*)&Ts[rr][col];
                float4 nr = *(const float4*)(g_nrm + b*NN + m0 + col);
                float4 o;
                o.x = fmaf(2.f, v.x, -nr.x);
                o.y = fmaf(2.f, v.y, -nr.y);
                o.z = fmaf(2.f, v.z, -nr.z);
                o.w = fmaf(2.f, v.w, -nr.w);
                *(float4*)(out + ((size_t)b*NN + grow)*NN + m0 + col) = o;
            }
        }
    }
}

// ---------- generic fp32 GEMM (ac / w6 / w7 / w8) ----------
__global__ void __launch_bounds__(256) k_gemm(
    const float* __restrict__ X, int sX,
    const float* __restrict__ W, int sW, long long wbs,
    float* __restrict__ Y, int sY, int K,
    float alpha, const float* __restrict__ vec, float beta, int vecStride,
    const float* __restrict__ s, const float* __restrict__ t, int act)
{
    __shared__ float Xs[2][16][128];
    __shared__ float Ws[2][16][128];
    const int tid = threadIdx.x;
    const int m0 = blockIdx.x * 128;
    const int o0 = blockIdx.y * 128;
    const int b  = m0 >> 11;
    const float* Wb = W + (long long)b * wbs;
    const int xm = tid & 127, xq = tid >> 7;
    const int tx = tid & 15,  ty = tid >> 4;
    const float* xrow = X  + (long long)(m0+xm)*sX;
    const float* wrow = Wb + (long long)(o0+xm)*sW;
    float acc[8][8] = {};

    float4 xa = *(const float4*)(xrow + xq*4);
    float4 xb = *(const float4*)(xrow + xq*4 + 8);
    float4 wa = *(const float4*)(wrow + xq*4);
    float4 wb = *(const float4*)(wrow + xq*4 + 8);
    #pragma unroll
    for (int u = 0; u < 4; u++) {
        Xs[0][xq*4+u][xm]   = (&xa.x)[u];
        Xs[0][xq*4+8+u][xm] = (&xb.x)[u];
        Ws[0][xq*4+u][xm]   = (&wa.x)[u];
        Ws[0][xq*4+8+u][xm] = (&wb.x)[u];
    }
    __syncthreads();
    int cur = 0;
    for (int k0 = 16; k0 < K; k0 += 16) {
        xa = *(const float4*)(xrow + k0 + xq*4);
        xb = *(const float4*)(xrow + k0 + xq*4 + 8);
        wa = *(const float4*)(wrow + k0 + xq*4);
        wb = *(const float4*)(wrow + k0 + xq*4 + 8);
        #pragma unroll
        for (int kk = 0; kk < 16; kk++) {
            float4 a0 = *(const float4*)&Xs[cur][kk][ty*4];
            float4 a1 = *(const float4*)&Xs[cur][kk][64+ty*4];
            float4 b0 = *(const float4*)&Ws[cur][kk][tx*4];
            float4 b1 = *(const float4*)&Ws[cur][kk][64+tx*4];
            float av[8] = {a0.x,a0.y,a0.z,a0.w,a1.x,a1.y,a1.z,a1.w};
            float bv[8] = {b0.x,b0.y,b0.z,b0.w,b1.x,b1.y,b1.z,b1.w};
            #pragma unroll
            for (int r = 0; r < 8; r++)
                #pragma unroll
                for (int c = 0; c < 8; c++)
                    acc[r][c] = fmaf(av[r], bv[c], acc[r][c]);
        }
        int nxt = cur ^ 1;
        #pragma unroll
        for (int u = 0; u < 4; u++) {
            Xs[nxt][xq*4+u][xm]   = (&xa.x)[u];
            Xs[nxt][xq*4+8+u][xm] = (&xb.x)[u];
            Ws[nxt][xq*4+u][xm]   = (&wa.x)[u];
            Ws[nxt][xq*4+8+u][xm] = (&wb.x)[u];
        }
        __syncthreads();
        cur = nxt;
    }
    #pragma unroll
    for (int kk = 0; kk < 16; kk++) {
        float4 a0 = *(const float4*)&Xs[cur][kk][ty*4];
        float4 a1 = *(const float4*)&Xs[cur][kk][64+ty*4];
        float4 b0 = *(const float4*)&Ws[cur][kk][tx*4];
        float4 b1 = *(const float4*)&Ws[cur][kk][64+tx*4];
        float av[8] = {a0.x,a0.y,a0.z,a0.w,a1.x,a1.y,a1.z,a1.w};
        float bv[8] = {b0.x,b0.y,b0.z,b0.w,b1.x,b1.y,b1.z,b1.w};
        #pragma unroll
        for (int r = 0; r < 8; r++)
            #pragma unroll
            for (int c = 0; c < 8; c++)
                acc[r][c] = fmaf(av[r], bv[c], acc[r][c]);
    }

    float vv[8] = {}, ss[8] = {}, tt[8] = {};
    if (vec) {
        *(float4*)&vv[0] = *(const float4*)(vec + b*vecStride + o0 + tx*4);
        *(float4*)&vv[4] = *(const float4*)(vec + b*vecStride + o0 + 64 + tx*4);
    }
    if (act) {
        *(float4*)&ss[0] = *(const float4*)(s + o0 + tx*4);
        *(float4*)&ss[4] = *(const float4*)(s + o0 + 64 + tx*4);
        *(float4*)&tt[0] = *(const float4*)(t + o0 + tx*4);
        *(float4*)&tt[4] = *(const float4*)(t + o0 + 64 + tx*4);
    }
    #pragma unroll
    for (int r = 0; r < 8; r++) {
        int m = m0 + (r < 4 ? ty*4 + r : 64 + ty*4 + r - 4);
        float o4[8];
        #pragma unroll
        for (int c = 0; c < 8; c++) {
            float a = alpha * acc[r][c];
            if (vec) a = fmaf(beta, vv[c], a);
            if (act) { a = fmaf(ss[c], a, tt[c]); a = a > 0.f ? a : 0.2f*a; }
            o4[c] = a;
        }
        *(float4*)(Y + (long long)m*sY + o0 + tx*4)      = *(float4*)&o4[0];
        *(float4*)(Y + (long long)m*sY + o0 + 64 + tx*4) = *(float4*)&o4[4];
    }
}

// per-row top-20, tournament style.
template<int COORD>
__global__ void __launch_bounds__(256) k_topk(const float* __restrict__ dist,
                                              int* __restrict__ idxo) {
    __shared__ float sv[NN];
    __shared__ float tmax[256];
    __shared__ int   targ[256];
    const int row = blockIdx.x, tid = threadIdx.x, b = row >> 11;
    if (COORD) {
        const float2* xp = (const float2*)g_xT + b*NN;
        float2 c = xp[row & 2047];
        for (int j = tid; j < NN; j += 256) {
            float2 q = xp[j];
            float dx = q.x - c.x, dy = q.y - c.y;
            sv[j] = -fmaf(dx, dx, dy*dy);
        }
    } else {
        const float* d = dist + (size_t)row * NN;
        for (int j = tid; j < NN; j += 256) sv[j] = d[j];
    }
    float lm = -INFINITY; int la = tid;
    for (int j = tid; j < NN; j += 256) {
        float v = sv[j];
        if (v > lm) { lm = v; la = j; }
    }
    tmax[tid] = lm; targ[tid] = la;
    __syncthreads();
    if (tid < 32) {
        for (int k = 0; k < KNBR; k++) {
            float bv = -INFINITY; int bt = tid;
            #pragma unroll
            for (int j = 0; j < 8; j++) {
                float v = tmax[tid + 32*j];
                if (v > bv) { bv = v; bt = tid + 32*j; }
            }
            #pragma unroll
            for (int off = 16; off; off >>= 1) {
                float ov = __shfl_down_sync(0xffffffffu, bv, off);
                int   ot = __shfl_down_sync(0xffffffffu, bt, off);
                if (ov > bv) { bv = ov; bt = ot; }
            }
            bt = __shfl_sync(0xffffffffu, bt, 0);
            if (tid == 0) {
                int gi = targ[bt];
                idxo[(size_t)row*KNBR + k] = gi;
                sv[gi] = -INFINITY;
                float lm2 = -INFINITY; int la2 = bt;
                for (int i = bt; i < NN; i += 256) {
                    float v = sv[i];
                    if (v > lm2) { lm2 = v; la2 = i; }
                }
                tmax[bt] = lm2; targ[bt] = la2;
            }
            __syncwarp();
        }
    }
}

// fused edge conv: 32 points/block; per-group named barriers inside the k loop.
template<bool TWO>
__global__ void __launch_bounds__(256) k_edge(
    const int* __restrict__ idx, const float* __restrict__ w2,
    const float* __restrict__ s1v, const float* __restrict__ t1v,
    const float* __restrict__ s2v, const float* __restrict__ t2v,
    float* __restrict__ outB, int outOff)
{
    __shared__ float W2s[64*65];
    __shared__ float h1T[4][64*8];
    const int tid = threadIdx.x;
    const int g = tid >> 6, o = tid & 63;
    const int n0 = blockIdx.x*32 + g*8;
    const int b  = n0 >> 11;
    if (TWO) for (int i = tid; i < 4096; i += 256) W2s[(i>>6)*65 + (i&63)] = w2[i];
    float cv[8], mv[8];
    #pragma unroll
    for (int p = 0; p < 8; p++) {
        cv[p] = g_ac[(size_t)(n0+p)*128 + 64 + o];
        mv[p] = -INFINITY;
    }
    const float ls1 = s1v[o], lt1 = t1v[o];
    float ls2 = 0.f, lt2 = 0.f;
    if (TWO) { ls2 = s2v[o]; lt2 = t2v[o]; __syncthreads(); }
    const int bar = g + 1;
    for (int k = 0; k < KNBR; k++) {
        float hv[8];
        #pragma unroll
        for (int p = 0; p < 8; p++) {
            int j = idx[(size_t)(n0+p)*KNBR + k];
            float aj = g_ac[(size_t)(b*NN + j)*128 + o];
            float h = fmaf(ls1, aj + cv[p], lt1);
            hv[p] = h > 0.f ? h : 0.2f*h;
        }
        if (TWO) {
            asm volatile("bar.sync %0, 64;" :: "r"(bar) : "memory");
            *(float4*)&h1T[g][o*8]   = make_float4(hv[0],hv[1],hv[2],hv[3]);
            *(float4*)&h1T[g][o*8+4] = make_float4(hv[4],hv[5],hv[6],hv[7]);
            asm volatile("bar.sync %0, 64;" :: "r"(bar) : "memory");
            float y[8] = {};
            #pragma unroll 8
            for (int c = 0; c < 64; c++) {
                float w = W2s[o*65 + c];
                float4 a0 = *(const float4*)&h1T[g][c*8];
                float4 a1 = *(const float4*)&h1T[g][c*8+4];
                y[0]=fmaf(w,a0.x,y[0]); y[1]=fmaf(w,a0.y,y[1]);
                y[2]=fmaf(w,a0.z,y[2]); y[3]=fmaf(w,a0.w,y[3]);
                y[4]=fmaf(w,a1.x,y[4]); y[5]=fmaf(w,a1.y,y[5]);
                y[6]=fmaf(w,a1.z,y[6]); y[7]=fmaf(w,a1.w,y[7]);
            }
            #pragma unroll
            for (int p = 0; p < 8; p++) {
                float z = fmaf(ls2, y[p], lt2);
                z = z > 0.f ? z : 0.2f*z;
                mv[p] = fmaxf(mv[p], z);
            }
        } else {
            #pragma unroll
            for (int p = 0; p < 8; p++) mv[p] = fmaxf(mv[p], hv[p]);
        }
    }
    #pragma unroll
    for (int p = 0; p < 8; p++) outB[(size_t)(n0+p)*192 + outOff + o] = mv[p];
}

__global__ void k_maxn1() {
    int o = blockIdx.x*256 + threadIdx.x;
    int b = blockIdx.y, ch = blockIdx.z;
    const float* p = g_big + (size_t)(b*NN + ch*256)*1024 + o;
    float m = -INFINITY;
    #pragma unroll 8
    for (int n = 0; n < 256; n++) m = fmaxf(m, p[(size_t)n*1024]);
    g_part[(b*8+ch)*1024 + o] = m;
}
__global__ void k_maxn2() {
    int o = blockIdx.x*256 + threadIdx.x;
    int b = blockIdx.y;
    float m = -INFINITY;
    #pragma unroll
    for (int ch = 0; ch < 8; ch++) m = fmaxf(m, g_part[(b*8+ch)*1024 + o]);
    g_gvec[b*1024 + o] = m;
}
__global__ void k_gproj(const float* __restrict__ w7) {
    int b = blockIdx.x, o = threadIdx.x;       // 512 threads
    __shared__ float gs[1024];
    for (int c = threadIdx.x; c < 1024; c += 512) gs[c] = g_gvec[b*1024 + c];
    __syncthreads();
    const float* wr = w7 + (size_t)o*1216;
    float a = 0.f;
    #pragma unroll 16
    for (int c = 0; c < 1024; c++) a = fmaf(wr[c], gs[c], a);
    g_gproj[b*512 + o] = a;
}
__global__ void k_final(const float* __restrict__ w9, const float* __restrict__ h8,
                        float* __restrict__ out) {
    int pt = blockIdx.x*8 + (threadIdx.x >> 5);
    int lane = threadIdx.x & 31;
    const float* r = h8 + (size_t)pt*256;
    float a = 0.f;
    #pragma unroll
    for (int u = 0; u < 8; u++) a = fmaf(r[lane + u*32], w9[lane + u*32], a);
    #pragma unroll
    for (int off = 16; off; off >>= 1) a += __shfl_down_sync(0xffffffffu, a, off);
    if (lane == 0) out[pt] = 1.f / (1.f + expf(-a));
}

extern "C" void kernel_launch(void* const* d_in, const int* in_sizes, int n_in,
                              void* d_out, int out_size)
{
    (void)in_sizes; (void)n_in; (void)out_size;
    const float* x = (const float*)d_in[0];
    const float *w1=(const float*)d_in[1], *w2=(const float*)d_in[2], *w3=(const float*)d_in[3],
                *w4=(const float*)d_in[4], *w5=(const float*)d_in[5], *w6=(const float*)d_in[6],
                *w7=(const float*)d_in[7], *w8=(const float*)d_in[8], *w9=(const float*)d_in[9];
    // metadata order follows setup_inputs() dict insertion: s/t INTERLEAVED: s1,t1,s2,t2,...
    const float *s1=(const float*)d_in[10], *t1=(const float*)d_in[11],
                *s2=(const float*)d_in[12], *t2=(const float*)d_in[13],
                *s3=(const float*)d_in[14], *t3=(const float*)d_in[15],
                *s4=(const float*)d_in[16], *t4=(const float*)d_in[17],
                *s5=(const float*)d_in[18], *t5=(const float*)d_in[19],
                *s6=(const float*)d_in[20], *t6=(const float*)d_in[21],
                *s7=(const float*)d_in[22], *t7=(const float*)d_in[23],
                *s8=(const float*)d_in[24], *t8=(const float*)d_in[25];
    float* out = (float*)d_out;

    float *p_catT, *p_big, *p_nrm, *p_wst, *p_gproj, *p_ac; int* p_idx;
    cudaGetSymbolAddress((void**)&p_catT,  g_catT);
    cudaGetSymbolAddress((void**)&p_big,   g_big);
    cudaGetSymbolAddress((void**)&p_nrm,   g_nrm);
    cudaGetSymbolAddress((void**)&p_wst,   g_wst);
    cudaGetSymbolAddress((void**)&p_gproj, g_gproj);
    cudaGetSymbolAddress((void**)&p_ac,    g_ac);
    cudaGetSymbolAddress((void**)&p_idx,   g_idx);
    float* p_h8 = p_big + (size_t)BN*512;

    k_prep_x<<<BN/256, 256>>>(x);
    // ---- stage 1 (C=2) ----
    k_topk<1><<<BN, 256>>>(nullptr, p_idx);
    k_ac1<<<BN*64/256, 256>>>(w1);
    k_edge<true><<<BN/32, 256>>>(p_idx, w2, s1, t1, s2, t2, p_catT, 0);
    // ---- stage 2 (input x1 = catT[:,0:64)) ----
    k_norm<<<BN/256, 256>>>(p_catT, 192);
    k_stack<<<16, 256>>>(w3);
    k_dist<<<dim3(136,16),256>>>(p_catT, 192, p_big);
    k_topk<0><<<BN, 256>>>(p_big, p_idx);
    k_gemm<<<dim3(256,1),256>>>(p_catT,192, p_wst,64,0,
                                p_ac,128, 64, 1.f, nullptr,0.f,0, nullptr,nullptr,0);
    k_edge<true><<<BN/32, 256>>>(p_idx, w4, s3, t3, s4, t4, p_catT, 64);
    // ---- stage 3 (input x2 = catT[:,64:128)) ----
    k_norm<<<BN/256, 256>>>(p_catT+64, 192);
    k_stack<<<16, 256>>>(w5);
    k_dist<<<dim3(136,16),256>>>(p_catT+64, 192, p_big);
    k_topk<0><<<BN, 256>>>(p_big, p_idx);
    k_gemm<<<dim3(256,1),256>>>(p_catT+64,192, p_wst,64,0,
                                p_ac,128, 64, 1.f, nullptr,0.f,0, nullptr,nullptr,0);
    k_edge<false><<<BN/32, 256>>>(p_idx, nullptr, s5, t5, nullptr, nullptr, p_catT, 128);
    // ---- head ----
    k_gemm<<<dim3(256,8),256>>>(p_catT,192, w6,192,0,
                                p_big,1024, 192, 1.f, nullptr,0.f,0, s6,t6,1);
    k_maxn1<<<dim3(4,16,8), 256>>>();
    k_maxn2<<<dim3(4,16), 256>>>();
    k_gproj<<<16, 512>>>(w7);
    k_gemm<<<dim3(256,4),256>>>(p_catT,192, w7+1024,1216,0,
                                p_big,512, 192, 1.f, p_gproj,1.f,512, s7,t7,1);
    k_gemm<<<dim3(256,2),256>>>(p_big,512, w8,512,0,
                                p_h8,256, 512, 1.f, nullptr,0.f,0, s8,t8,1);
    k_final<<<BN/8, 256>>>(w9, p_h8, out);
}